// round 7
// baseline (speedup 1.0000x reference)
#include <cuda_runtime.h>
#include <cuda_bf16.h>
#include <cstdint>

#define N_ATOMS   50000
#define N_BONDS   100000
#define MAX_NB    6
#define ATOM_FDIM 133
#define BOND_FDIM 147
#define HIDDEN    300
#define DEPTH     3

// padded K per GEMM (multiples of 64)
#define K0P 192   // bond_fdim 147 -> 192
#define K1P 320   // hidden 300 -> 320
#define K2P 448   // 300 + 133 = 433 -> 448  (A order: [amsg | f_atoms | pad])
#define NBP 384   // padded N for weight buffers

// ---------------- scratch (static device globals; no allocation) ----------------
__device__ float  g_inp [(size_t)N_BONDS * HIDDEN];
__device__ float  g_msg [(size_t)N_BONDS * HIDDEN];
__device__ float  g_amsg[(size_t)N_ATOMS * HIDDEN];
__device__ float  g_ah  [(size_t)N_ATOMS * HIDDEN];
__device__ __align__(16) ushort gA0h[(size_t)N_BONDS * K0P], gA0l[(size_t)N_BONDS * K0P];
__device__ __align__(16) ushort gA1h[(size_t)N_BONDS * K1P], gA1l[(size_t)N_BONDS * K1P];
__device__ __align__(16) ushort gA2h[(size_t)N_ATOMS * K2P], gA2l[(size_t)N_ATOMS * K2P];
__device__ __align__(16) ushort gWh [(size_t)K2P * NBP],     gWl [(size_t)K2P * NBP];

// ---------------- helpers ----------------
__device__ __forceinline__ uint32_t smem_u32(const void* p) {
    uint32_t a;
    asm("{ .reg .u64 t; cvta.to.shared.u64 t, %1; cvt.u32.u64 %0, t; }" : "=r"(a) : "l"(p));
    return a;
}
__device__ __forceinline__ void ldsm4(uint32_t* r, uint32_t addr) {
    asm volatile("ldmatrix.sync.aligned.m8n8.x4.shared.b16 {%0,%1,%2,%3}, [%4];"
        : "=r"(r[0]), "=r"(r[1]), "=r"(r[2]), "=r"(r[3]) : "r"(addr));
}
__device__ __forceinline__ void ldsm4t(uint32_t* r, uint32_t addr) {
    asm volatile("ldmatrix.sync.aligned.m8n8.x4.trans.shared.b16 {%0,%1,%2,%3}, [%4];"
        : "=r"(r[0]), "=r"(r[1]), "=r"(r[2]), "=r"(r[3]) : "r"(addr));
}
__device__ __forceinline__ void mma16816(float* c, const uint32_t* a, uint32_t b0, uint32_t b1) {
    asm volatile("mma.sync.aligned.m16n8k16.row.col.f32.bf16.bf16.f32 "
        "{%0,%1,%2,%3}, {%4,%5,%6,%7}, {%8,%9}, {%0,%1,%2,%3};"
        : "+f"(c[0]), "+f"(c[1]), "+f"(c[2]), "+f"(c[3])
        : "r"(a[0]), "r"(a[1]), "r"(a[2]), "r"(a[3]), "r"(b0), "r"(b1));
}
__device__ __forceinline__ void cp16(uint32_t dst, const void* src, bool pred) {
    asm volatile("cp.async.cg.shared.global [%0], [%1], 16, %2;"
        :: "r"(dst), "l"(src), "r"(pred ? 16 : 0) : "memory");
}
__device__ __forceinline__ void split_bf16(float v, ushort& h, ushort& l) {
    __nv_bfloat16 hb = __float2bfloat16(v);
    __nv_bfloat16 lb = __float2bfloat16(v - __bfloat162float(hb));
    h = __bfloat16_as_ushort(hb); l = __bfloat16_as_ushort(lb);
}

// ---------------- smem layout (BK = 64) ----------------
constexpr int SA = 72, SB = 136;                 // bf16 elem strides (ldmatrix-safe pads)
constexpr int A_STG = 128 * SA * 2;              // 18432 B (128 rows x 64 cols)
constexpr int B_STG = 64 * SB * 2;               // 17408 B (64 rows x 128 cols)
constexpr int OFF_AH = 0;
constexpr int OFF_AL = 2 * A_STG;                // 36864
constexpr int OFF_BH = 4 * A_STG;                // 73728
constexpr int OFF_BL = OFF_BH + 2 * B_STG;       // 108544
constexpr int SMEM_BYTES = OFF_BL + 2 * B_STG;   // 143360

// ---------------- pipelined bf16 HMMA GEMM ----------------
// C[M x 300] = epi(A @ B); A/B bf16 hi/lo device-global buffers picked by MODE.
// BM=128, BN=128, BK=64; 256 threads (8 warps: 4 m-warps x 2 n-warps).
// MODE 0: A=gA0 (K=192); g_inp=acc, g_msg=relu(acc)
// MODE 1: A=gA1 (K=320); g_msg=relu(g_inp+acc)
// MODE 2: A=gA2 (K=448); g_ah =relu(acc+bias)
template<int MODE>
__global__ void __launch_bounds__(256) gemm_bf16(const float* __restrict__ bias, int M)
{
    constexpr int K = (MODE == 0) ? K0P : (MODE == 1) ? K1P : K2P;
    const ushort* __restrict__ Ahi = (MODE == 0) ? gA0h : (MODE == 1) ? gA1h : gA2h;
    const ushort* __restrict__ Alo = (MODE == 0) ? gA0l : (MODE == 1) ? gA1l : gA2l;

    extern __shared__ char sm[];
    const uint32_t sb = smem_u32(sm);
    const int tid = threadIdx.x, lane = tid & 31, wid = tid >> 5;
    const int m0 = blockIdx.y * 128, n0 = blockIdx.x * 128;
    const int wm = wid & 3, wn = wid >> 2;

    float acc[2][8][4];
    #pragma unroll
    for (int i = 0; i < 2; i++)
        #pragma unroll
        for (int j = 0; j < 8; j++)
            #pragma unroll
            for (int q = 0; q < 4; q++) acc[i][j][q] = 0.f;

    constexpr int niter = K / 64;

    auto issue = [&](int it) {
        const int st = it & 1;
        const int k0 = it * 64;
        // A: 1024 x 16B chunks per array (row = 8 chunks of 8 bf16)
        #pragma unroll
        for (int i = 0; i < 4; i++) {
            int q = i * 256 + tid;
            int row = q >> 3, c16 = q & 7;
            int gm = m0 + row;
            bool p = gm < M;
            size_t so = (size_t)(p ? gm : 0) * K + k0 + c16 * 8;
            uint32_t doff = (uint32_t)(row * SA + c16 * 8) * 2;
            cp16(sb + OFF_AH + st * A_STG + doff, Ahi + so, p);
            cp16(sb + OFF_AL + st * A_STG + doff, Alo + so, p);
        }
        // B: 1024 x 16B chunks per array (rows k0..k0+63 all < K; cols padded to NBP)
        #pragma unroll
        for (int i = 0; i < 4; i++) {
            int q = i * 256 + tid;
            int row = q >> 4, c16 = q & 15;
            size_t so = (size_t)(k0 + row) * NBP + n0 + c16 * 8;
            uint32_t doff = (uint32_t)(row * SB + c16 * 8) * 2;
            cp16(sb + OFF_BH + st * B_STG + doff, gWh + so, true);
            cp16(sb + OFF_BL + st * B_STG + doff, gWl + so, true);
        }
        asm volatile("cp.async.commit_group;" ::: "memory");
    };

    issue(0);
    for (int it = 0; it < niter; it++) {
        if (it + 1 < niter) {
            issue(it + 1);
            asm volatile("cp.async.wait_group 1;" ::: "memory");
        } else {
            asm volatile("cp.async.wait_group 0;" ::: "memory");
        }
        __syncthreads();

        const int st = it & 1;
        const uint32_t aH = sb + OFF_AH + st * A_STG, aL = sb + OFF_AL + st * A_STG;
        const uint32_t bH = sb + OFF_BH + st * B_STG, bL = sb + OFF_BL + st * B_STG;
        #pragma unroll
        for (int ks = 0; ks < 4; ks++) {
            uint32_t ah[2][4], al[2][4], bh[4][4], bl[4][4];
            const int arow = wm * 32 + (lane & 15);
            const int acol = ks * 16 + (lane >> 4) * 8;
            #pragma unroll
            for (int mi = 0; mi < 2; mi++) {
                uint32_t off = (uint32_t)((arow + mi * 16) * SA + acol) * 2;
                ldsm4(ah[mi], aH + off);
                ldsm4(al[mi], aL + off);
            }
            const int bkrow = ks * 16 + (lane & 15);
            const int bncol = wn * 64 + (lane >> 4) * 8;
            #pragma unroll
            for (int ni = 0; ni < 4; ni++) {
                uint32_t off = (uint32_t)(bkrow * SB + bncol + ni * 16) * 2;
                ldsm4t(bh[ni], bH + off);
                ldsm4t(bl[ni], bL + off);
            }
            #pragma unroll
            for (int mi = 0; mi < 2; mi++) {
                #pragma unroll
                for (int p = 0; p < 4; p++) {
                    mma16816(acc[mi][2*p],   ah[mi], bh[p][0], bh[p][1]);
                    mma16816(acc[mi][2*p],   ah[mi], bl[p][0], bl[p][1]);
                    mma16816(acc[mi][2*p],   al[mi], bh[p][0], bh[p][1]);
                    mma16816(acc[mi][2*p+1], ah[mi], bh[p][2], bh[p][3]);
                    mma16816(acc[mi][2*p+1], ah[mi], bl[p][2], bl[p][3]);
                    mma16816(acc[mi][2*p+1], al[mi], bh[p][2], bh[p][3]);
                }
            }
        }
        __syncthreads();
    }

    // ---- epilogue ----
    #pragma unroll
    for (int mi = 0; mi < 2; mi++) {
        #pragma unroll
        for (int t8 = 0; t8 < 8; t8++) {
            int col = n0 + wn * 64 + t8 * 8 + (lane & 3) * 2;
            #pragma unroll
            for (int h = 0; h < 2; h++) {
                int r = m0 + wm * 32 + mi * 16 + (lane >> 2) + h * 8;
                if (r >= M) continue;
                #pragma unroll
                for (int e = 0; e < 2; e++) {
                    int cn = col + e;
                    if (cn >= HIDDEN) continue;
                    float v = acc[mi][t8][2*h + e];
                    size_t o = (size_t)r * HIDDEN + cn;
                    if (MODE == 0)      { g_inp[o] = v; g_msg[o] = fmaxf(v, 0.f); }
                    else if (MODE == 1) { g_msg[o] = fmaxf(g_inp[o] + v, 0.f); }
                    else                { g_ah[o]  = fmaxf(v + bias[cn], 0.f); }
                }
            }
        }
    }
}

// ---------------- weight converters: W[K x 300] fp32 -> gW hi/lo [Kp x NBP] ----------------
__global__ void conv_w(const float* __restrict__ W, int K, int Kp)
{
    int idx = blockIdx.x * blockDim.x + threadIdx.x;
    if (idx >= Kp * NBP) return;
    int k = idx / NBP, n = idx - k * NBP;
    float v = (k < K && n < HIDDEN) ? W[(size_t)k * HIDDEN + n] : 0.f;
    ushort h, l; split_bf16(v, h, l);
    gWh[idx] = h; gWl[idx] = l;
}
// W_o remap: row k<300 -> W_o[133+k] (amsg part); 300<=k<433 -> W_o[k-300] (f_atoms)
__global__ void conv_w_o(const float* __restrict__ W)
{
    int idx = blockIdx.x * blockDim.x + threadIdx.x;
    if (idx >= K2P * NBP) return;
    int k = idx / NBP, n = idx - k * NBP;
    int src = (k < HIDDEN) ? (ATOM_FDIM + k) : (k < HIDDEN + ATOM_FDIM ? k - HIDDEN : -1);
    float v = (src >= 0 && n < HIDDEN) ? W[(size_t)src * HIDDEN + n] : 0.f;
    ushort h, l; split_bf16(v, h, l);
    gWh[idx] = h; gWl[idx] = l;
}

// ---------------- f_bonds -> gA0 ----------------
__global__ void conv_fbonds(const float* __restrict__ F)
{
    int idx = blockIdx.x * blockDim.x + threadIdx.x;
    if (idx >= N_BONDS * K0P) return;
    int r = idx / K0P, c = idx - r * K0P;
    float v = (c < BOND_FDIM) ? F[(size_t)r * BOND_FDIM + c] : 0.f;
    ushort h, l; split_bf16(v, h, l);
    gA0h[idx] = h; gA0l[idx] = l;
}
// ---------------- f_atoms -> gA2 cols [300..447] (133 feats + 15 pad) ----------------
__global__ void conv_fatoms(const float* __restrict__ F)
{
    constexpr int C = K2P - HIDDEN;  // 148
    int idx = blockIdx.x * blockDim.x + threadIdx.x;
    if (idx >= N_ATOMS * C) return;
    int a = idx / C, c = idx - a * C;
    float v = (c < ATOM_FDIM) ? F[(size_t)a * ATOM_FDIM + c] : 0.f;
    ushort h, l; split_bf16(v, h, l);
    size_t o = (size_t)a * K2P + HIDDEN + c;
    gA2h[o] = h; gA2l[o] = l;
}

// ---------------- atom_sum: a_msg[a] = sum_k g_msg[a2b[a][k]] ----------------
// FIN=false -> g_amsg fp32; FIN=true -> bf16 hi/lo into gA2 cols [0..300)
template<bool FIN>
__global__ void __launch_bounds__(256) atom_sum(const int* __restrict__ a2b)
{
    constexpr int HV = HIDDEN / 4;
    int idx = blockIdx.x * blockDim.x + threadIdx.x;
    if (idx >= N_ATOMS * HV) return;
    int a = idx / HV;
    int j = idx - a * HV;
    const float4* m4 = (const float4*)g_msg;
    float4 s = make_float4(0.f, 0.f, 0.f, 0.f);
    #pragma unroll
    for (int k = 0; k < MAX_NB; k++) {
        int b = __ldg(&a2b[a * MAX_NB + k]);
        float4 v = m4[(size_t)b * HV + j];
        s.x += v.x; s.y += v.y; s.z += v.z; s.w += v.w;
    }
    if (!FIN) {
        ((float4*)g_amsg)[idx] = s;
    } else {
        ushort4 hh, ll;
        split_bf16(s.x, hh.x, ll.x); split_bf16(s.y, hh.y, ll.y);
        split_bf16(s.z, hh.z, ll.z); split_bf16(s.w, hh.w, ll.w);
        size_t o = (size_t)a * K2P + j * 4;
        *(ushort4*)&gA2h[o] = hh;
        *(ushort4*)&gA2l[o] = ll;
    }
}

// ---------------- bond_msg: gA1 = split_bf16(a_msg[b2a] - msg[b2revb]) ----------------
__global__ void __launch_bounds__(256) bond_msg(
    const int* __restrict__ b2a, const int* __restrict__ b2revb)
{
    constexpr int G = K1P / 4;   // 80 groups of 4 cols
    int idx = blockIdx.x * blockDim.x + threadIdx.x;
    if (idx >= N_BONDS * G) return;
    int m = idx / G;
    int g = idx - m * G;
    size_t o = (size_t)m * K1P + g * 4;
    if (g < HIDDEN / 4) {
        float4 av = ((const float4*)g_amsg)[(size_t)__ldg(&b2a[m])    * (HIDDEN/4) + g];
        float4 rv = ((const float4*)g_msg )[(size_t)__ldg(&b2revb[m]) * (HIDDEN/4) + g];
        float4 d = make_float4(av.x - rv.x, av.y - rv.y, av.z - rv.z, av.w - rv.w);
        ushort4 hh, ll;
        split_bf16(d.x, hh.x, ll.x); split_bf16(d.y, hh.y, ll.y);
        split_bf16(d.z, hh.z, ll.z); split_bf16(d.w, hh.w, ll.w);
        *(ushort4*)&gA1h[o] = hh;
        *(ushort4*)&gA1l[o] = ll;
    } else {
        ushort4 z = make_ushort4(0, 0, 0, 0);
        *(ushort4*)&gA1h[o] = z;
        *(ushort4*)&gA1l[o] = z;
    }
}

// ---------------- per-molecule mean (mol_id sorted; deterministic) ----------------
__global__ void mol_mean(const int* __restrict__ mol_id, float* __restrict__ out)
{
    int mol = blockIdx.x;
    int lo = 0, hi = N_ATOMS;
    while (lo < hi) { int mid = (lo + hi) >> 1; if (mol_id[mid] < mol) lo = mid + 1; else hi = mid; }
    int start = lo;
    hi = N_ATOMS;
    while (lo < hi) { int mid = (lo + hi) >> 1; if (mol_id[mid] < mol + 1) lo = mid + 1; else hi = mid; }
    int end = lo;
    float inv = (end > start) ? 1.0f / (float)(end - start) : 0.0f;
    for (int j = threadIdx.x; j < HIDDEN; j += blockDim.x) {
        float s = 0.f;
        for (int a = start; a < end; a++) s += g_ah[(size_t)a * HIDDEN + j];
        out[(size_t)mol * HIDDEN + j] = s * inv;
    }
}

// ---------------- launch ----------------
extern "C" void kernel_launch(void* const* d_in, const int* in_sizes, int n_in,
                              void* d_out, int out_size)
{
    const float* f_atoms = (const float*)d_in[0];
    const float* f_bonds = (const float*)d_in[1];
    const int*   a2b     = (const int*)  d_in[2];
    const int*   b2a     = (const int*)  d_in[3];
    const int*   b2revb  = (const int*)  d_in[4];
    const int*   mol_id  = (const int*)  d_in[5];
    int wbase = (n_in >= 11 && in_sizes[6] == 1) ? 7 : 6;
    const float* W_i = (const float*)d_in[wbase + 0];
    const float* W_h = (const float*)d_in[wbase + 1];
    const float* W_o = (const float*)d_in[wbase + 2];
    const float* b_o = (const float*)d_in[wbase + 3];
    float* out = (float*)d_out;
    int n_mols = out_size / HIDDEN;

    cudaFuncSetAttribute(gemm_bf16<0>, cudaFuncAttributeMaxDynamicSharedMemorySize, SMEM_BYTES);
    cudaFuncSetAttribute(gemm_bf16<1>, cudaFuncAttributeMaxDynamicSharedMemorySize, SMEM_BYTES);
    cudaFuncSetAttribute(gemm_bf16<2>, cudaFuncAttributeMaxDynamicSharedMemorySize, SMEM_BYTES);

    dim3 gb(3, (N_BONDS + 127) / 128);
    dim3 ga(3, (N_ATOMS + 127) / 128);
    int atom_blocks = (N_ATOMS * (HIDDEN/4) + 255) / 256;
    int bond_blocks = (N_BONDS * (K1P/4) + 255) / 256;

    // GEMM 0: message = relu(inp = f_bonds @ W_i)
    conv_w<<<(K0P * NBP + 255) / 256, 256>>>(W_i, BOND_FDIM, K0P);
    conv_fbonds<<<((size_t)N_BONDS * K0P + 255) / 256, 256>>>(f_bonds);
    gemm_bf16<0><<<gb, 256, SMEM_BYTES>>>(nullptr, N_BONDS);

    // depth loop: message = relu(inp + (a_msg[b2a]-msg[b2revb]) @ W_h)
    conv_w<<<(K1P * NBP + 255) / 256, 256>>>(W_h, HIDDEN, K1P);
    for (int d = 0; d < DEPTH - 1; d++) {
        atom_sum<false><<<atom_blocks, 256>>>(a2b);
        bond_msg<<<bond_blocks, 256>>>(b2a, b2revb);
        gemm_bf16<1><<<gb, 256, SMEM_BYTES>>>(nullptr, N_BONDS);
    }

    // readout: atom_hiddens = relu(concat @ W_o + b_o)
    atom_sum<true><<<atom_blocks, 256>>>(a2b);
    conv_fatoms<<<((size_t)N_ATOMS * (K2P - HIDDEN) + 255) / 256, 256>>>(f_atoms);
    conv_w_o<<<(K2P * NBP + 255) / 256, 256>>>(W_o);
    gemm_bf16<2><<<ga, 256, SMEM_BYTES>>>(b_o, N_ATOMS);

    mol_mean<<<n_mols, 128>>>(mol_id, out);
}

// round 8
// speedup vs baseline: 1.0374x; 1.0374x over previous
#include <cuda_runtime.h>
#include <cuda_bf16.h>
#include <cstdint>

#define N_ATOMS   50000
#define N_BONDS   100000
#define MAX_NB    6
#define ATOM_FDIM 133
#define BOND_FDIM 147
#define HIDDEN    300
#define DEPTH     3

// padded K per GEMM (multiples of 32)
#define K0P 160   // bond_fdim 147 -> 160
#define K1P 320   // hidden 300 -> 320
#define K2P 448   // 300 + 133 = 433 -> 448  (A order: [amsg | f_atoms | pad])
#define NBP 384   // padded N for weight buffers

// ---------------- scratch (static device globals; no allocation) ----------------
__device__ float  g_inp [(size_t)N_BONDS * HIDDEN];   // W_i result (pre-activation)
__device__ float  g_msg [(size_t)N_BONDS * HIDDEN];   // pre-activation messages (depth loop)
__device__ float  g_amsg[(size_t)N_ATOMS * HIDDEN];
__device__ float  g_ah  [(size_t)N_ATOMS * HIDDEN];
__device__ __align__(16) ushort gA0h[(size_t)N_BONDS * K0P], gA0l[(size_t)N_BONDS * K0P];
__device__ __align__(16) ushort gA1h[(size_t)N_BONDS * K1P], gA1l[(size_t)N_BONDS * K1P];
__device__ __align__(16) ushort gA2h[(size_t)N_ATOMS * K2P], gA2l[(size_t)N_ATOMS * K2P];
__device__ __align__(16) ushort gWh [(size_t)K2P * NBP],     gWl [(size_t)K2P * NBP];

// ---------------- helpers ----------------
__device__ __forceinline__ uint32_t smem_u32(const void* p) {
    uint32_t a;
    asm("{ .reg .u64 t; cvta.to.shared.u64 t, %1; cvt.u32.u64 %0, t; }" : "=r"(a) : "l"(p));
    return a;
}
__device__ __forceinline__ void ldsm4(uint32_t* r, uint32_t addr) {
    asm volatile("ldmatrix.sync.aligned.m8n8.x4.shared.b16 {%0,%1,%2,%3}, [%4];"
        : "=r"(r[0]), "=r"(r[1]), "=r"(r[2]), "=r"(r[3]) : "r"(addr));
}
__device__ __forceinline__ void ldsm4t(uint32_t* r, uint32_t addr) {
    asm volatile("ldmatrix.sync.aligned.m8n8.x4.trans.shared.b16 {%0,%1,%2,%3}, [%4];"
        : "=r"(r[0]), "=r"(r[1]), "=r"(r[2]), "=r"(r[3]) : "r"(addr));
}
__device__ __forceinline__ void mma16816(float* c, const uint32_t* a, uint32_t b0, uint32_t b1) {
    asm volatile("mma.sync.aligned.m16n8k16.row.col.f32.bf16.bf16.f32 "
        "{%0,%1,%2,%3}, {%4,%5,%6,%7}, {%8,%9}, {%0,%1,%2,%3};"
        : "+f"(c[0]), "+f"(c[1]), "+f"(c[2]), "+f"(c[3])
        : "r"(a[0]), "r"(a[1]), "r"(a[2]), "r"(a[3]), "r"(b0), "r"(b1));
}
__device__ __forceinline__ void cp16(uint32_t dst, const void* src, bool pred) {
    asm volatile("cp.async.cg.shared.global [%0], [%1], 16, %2;"
        :: "r"(dst), "l"(src), "r"(pred ? 16 : 0) : "memory");
}
__device__ __forceinline__ void split_bf16(float v, ushort& h, ushort& l) {
    __nv_bfloat16 hb = __float2bfloat16(v);
    __nv_bfloat16 lb = __float2bfloat16(v - __bfloat162float(hb));
    h = __bfloat16_as_ushort(hb); l = __bfloat16_as_ushort(lb);
}

// ---------------- smem layout (BK = 32, 3 stages) ----------------
constexpr int SA = 40, SB = 136;                 // bf16 elem strides (ldmatrix pads)
constexpr int A_TB = 128 * SA * 2;               // 10240 B
constexpr int B_TB = 32 * SB * 2;                // 8704 B
constexpr int ST_AH = 0;
constexpr int ST_AL = A_TB;                      // 10240
constexpr int ST_BH = 2 * A_TB;                  // 20480
constexpr int ST_BL = 2 * A_TB + B_TB;           // 29184
constexpr int STG   = 2 * A_TB + 2 * B_TB;       // 37888 per stage
constexpr int SMEM_BYTES = 3 * STG;              // 113664

// ---------------- pipelined bf16 HMMA GEMM ----------------
// C[M x 300] = epi(A @ B); A/B bf16 hi/lo device-global buffers picked by MODE.
// BM=128, BN=128, BK=32; 256 threads (8 warps: 4 m-warps x 2 n-warps).
// n-tile at blockIdx.x==2 is "half": only cols 0..43 live (global 256..299).
// MODE 0: A=gA0 (K=160); g_inp = acc                  (pre-activation)
// MODE 1: A=gA1 (K=320); g_msg = g_inp + acc          (pre-activation)
// MODE 2: A=gA2 (K=448); g_ah  = relu(acc + bias)
template<int MODE>
__global__ void __launch_bounds__(256) gemm_bf16(const float* __restrict__ bias, int M)
{
    constexpr int K = (MODE == 0) ? K0P : (MODE == 1) ? K1P : K2P;
    const ushort* __restrict__ Ahi = (MODE == 0) ? gA0h : (MODE == 1) ? gA1h : gA2h;
    const ushort* __restrict__ Alo = (MODE == 0) ? gA0l : (MODE == 1) ? gA1l : gA2l;

    extern __shared__ char sm[];
    const uint32_t sb = smem_u32(sm);
    const int tid = threadIdx.x, lane = tid & 31, wid = tid >> 5;
    const int m0 = blockIdx.y * 128, n0 = blockIdx.x * 128;
    const bool half = (blockIdx.x == 2);
    const int wm = wid & 3, wn = wid >> 2;

    float acc[2][8][4];
    #pragma unroll
    for (int i = 0; i < 2; i++)
        #pragma unroll
        for (int j = 0; j < 8; j++)
            #pragma unroll
            for (int q = 0; q < 4; q++) acc[i][j][q] = 0.f;

    constexpr int niter = K / 32;

    auto issue = [&](int it) {
        const uint32_t so_st = sb + (uint32_t)(it % 3) * STG;
        const int k0 = it * 32;
        // A: 512 x 16B chunks per array (row = 4 chunks of 8 bf16)
        #pragma unroll
        for (int i = 0; i < 2; i++) {
            int q = i * 256 + tid;
            int row = q >> 2, c16 = q & 3;
            int gm = m0 + row;
            bool p = gm < M;
            size_t so = (size_t)(p ? gm : 0) * K + k0 + c16 * 8;
            uint32_t doff = (uint32_t)(row * SA + c16 * 8) * 2;
            cp16(so_st + ST_AH + doff, Ahi + so, p);
            cp16(so_st + ST_AL + doff, Alo + so, p);
        }
        // B: 512 x 16B chunks per array; half tile only needs cols < 48
        #pragma unroll
        for (int i = 0; i < 2; i++) {
            int q = i * 256 + tid;
            int row = q >> 4, c16 = q & 15;
            bool bp = !half || (c16 < 6);
            size_t so = (size_t)(k0 + row) * NBP + n0 + c16 * 8;
            uint32_t doff = (uint32_t)(row * SB + c16 * 8) * 2;
            cp16(so_st + ST_BH + doff, gWh + so, bp);
            cp16(so_st + ST_BL + doff, gWl + so, bp);
        }
        asm volatile("cp.async.commit_group;" ::: "memory");
    };

    issue(0);
    if (niter > 1) issue(1);
    for (int it = 0; it < niter; it++) {
        if (it + 2 < niter) {
            issue(it + 2);
            asm volatile("cp.async.wait_group 2;" ::: "memory");
        } else if (it + 1 < niter) {
            asm volatile("cp.async.wait_group 1;" ::: "memory");
        } else {
            asm volatile("cp.async.wait_group 0;" ::: "memory");
        }
        __syncthreads();

        const uint32_t st = sb + (uint32_t)(it % 3) * STG;
        const uint32_t aH = st + ST_AH, aL = st + ST_AL;
        const uint32_t bH = st + ST_BH, bL = st + ST_BL;
        if (!(half && wn == 1)) {
            #pragma unroll
            for (int ks = 0; ks < 2; ks++) {
                uint32_t ah[2][4], al[2][4], bh[4][4], bl[4][4];
                const int arow = wm * 32 + (lane & 15);
                const int acol = ks * 16 + (lane >> 4) * 8;
                #pragma unroll
                for (int mi = 0; mi < 2; mi++) {
                    uint32_t off = (uint32_t)((arow + mi * 16) * SA + acol) * 2;
                    ldsm4(ah[mi], aH + off);
                    ldsm4(al[mi], aL + off);
                }
                const int bkrow = ks * 16 + (lane & 15);
                const int bncol = wn * 64 + (lane >> 4) * 8;
                #pragma unroll
                for (int ni = 0; ni < 4; ni++) {
                    if (half && ni == 3) continue;
                    uint32_t off = (uint32_t)(bkrow * SB + bncol + ni * 16) * 2;
                    ldsm4t(bh[ni], bH + off);
                    ldsm4t(bl[ni], bL + off);
                }
                #pragma unroll
                for (int mi = 0; mi < 2; mi++) {
                    #pragma unroll
                    for (int p = 0; p < 4; p++) {
                        if (half && p == 3) continue;
                        mma16816(acc[mi][2*p],   ah[mi], bh[p][0], bh[p][1]);
                        mma16816(acc[mi][2*p],   ah[mi], bl[p][0], bl[p][1]);
                        mma16816(acc[mi][2*p],   al[mi], bh[p][0], bh[p][1]);
                        mma16816(acc[mi][2*p+1], ah[mi], bh[p][2], bh[p][3]);
                        mma16816(acc[mi][2*p+1], ah[mi], bl[p][2], bl[p][3]);
                        mma16816(acc[mi][2*p+1], al[mi], bh[p][2], bh[p][3]);
                    }
                }
            }
        }
        __syncthreads();
    }

    // ---- epilogue ----
    #pragma unroll
    for (int mi = 0; mi < 2; mi++) {
        #pragma unroll
        for (int t8 = 0; t8 < 8; t8++) {
            int col = n0 + wn * 64 + t8 * 8 + (lane & 3) * 2;
            #pragma unroll
            for (int h = 0; h < 2; h++) {
                int r = m0 + wm * 32 + mi * 16 + (lane >> 2) + h * 8;
                if (r >= M) continue;
                #pragma unroll
                for (int e = 0; e < 2; e++) {
                    int cn = col + e;
                    if (cn >= HIDDEN) continue;
                    float v = acc[mi][t8][2*h + e];
                    size_t o = (size_t)r * HIDDEN + cn;
                    if (MODE == 0)      { g_inp[o] = v; }
                    else if (MODE == 1) { g_msg[o] = g_inp[o] + v; }
                    else                { g_ah[o]  = fmaxf(v + bias[cn], 0.f); }
                }
            }
        }
    }
}

// ---------------- weight converters: W[K x 300] fp32 -> gW hi/lo [Kp x NBP] ----------------
__global__ void conv_w(const float* __restrict__ W, int K, int Kp)
{
    int idx = blockIdx.x * blockDim.x + threadIdx.x;
    if (idx >= Kp * NBP) return;
    int k = idx / NBP, n = idx - k * NBP;
    float v = (k < K && n < HIDDEN) ? W[(size_t)k * HIDDEN + n] : 0.f;
    ushort h, l; split_bf16(v, h, l);
    gWh[idx] = h; gWl[idx] = l;
}
// W_o remap: row k<300 -> W_o[133+k] (amsg part); 300<=k<433 -> W_o[k-300] (f_atoms)
__global__ void conv_w_o(const float* __restrict__ W)
{
    int idx = blockIdx.x * blockDim.x + threadIdx.x;
    if (idx >= K2P * NBP) return;
    int k = idx / NBP, n = idx - k * NBP;
    int src = (k < HIDDEN) ? (ATOM_FDIM + k) : (k < HIDDEN + ATOM_FDIM ? k - HIDDEN : -1);
    float v = (src >= 0 && n < HIDDEN) ? W[(size_t)src * HIDDEN + n] : 0.f;
    ushort h, l; split_bf16(v, h, l);
    gWh[idx] = h; gWl[idx] = l;
}

// ---------------- f_bonds -> gA0 ----------------
__global__ void conv_fbonds(const float* __restrict__ F)
{
    int idx = blockIdx.x * blockDim.x + threadIdx.x;
    if (idx >= N_BONDS * K0P) return;
    int r = idx / K0P, c = idx - r * K0P;
    float v = (c < BOND_FDIM) ? F[(size_t)r * BOND_FDIM + c] : 0.f;
    ushort h, l; split_bf16(v, h, l);
    gA0h[idx] = h; gA0l[idx] = l;
}
// ---------------- f_atoms -> gA2 cols [300..447] (133 feats + 15 pad) ----------------
__global__ void conv_fatoms(const float* __restrict__ F)
{
    constexpr int C = K2P - HIDDEN;  // 148
    int idx = blockIdx.x * blockDim.x + threadIdx.x;
    if (idx >= N_ATOMS * C) return;
    int a = idx / C, c = idx - a * C;
    float v = (c < ATOM_FDIM) ? F[(size_t)a * ATOM_FDIM + c] : 0.f;
    ushort h, l; split_bf16(v, h, l);
    size_t o = (size_t)a * K2P + HIDDEN + c;
    gA2h[o] = h; gA2l[o] = l;
}

// ---------------- atom_sum: a_msg[a] = sum_k relu(src[a2b[a][k]]) ----------------
// SRC 0 -> g_inp (depth iter 0), SRC 1 -> g_msg.
// FIN=false -> g_amsg fp32; FIN=true -> bf16 hi/lo into gA2 cols [0..300)
template<bool FIN, int SRC>
__global__ void __launch_bounds__(256) atom_sum(const int* __restrict__ a2b)
{
    constexpr int HV = HIDDEN / 4;
    const float* __restrict__ src = (SRC == 0) ? g_inp : g_msg;
    int idx = blockIdx.x * blockDim.x + threadIdx.x;
    if (idx >= N_ATOMS * HV) return;
    int a = idx / HV;
    int j = idx - a * HV;
    const float4* m4 = (const float4*)src;
    float4 s = make_float4(0.f, 0.f, 0.f, 0.f);
    #pragma unroll
    for (int k = 0; k < MAX_NB; k++) {
        int b = __ldg(&a2b[a * MAX_NB + k]);
        float4 v = m4[(size_t)b * HV + j];
        s.x += fmaxf(v.x, 0.f); s.y += fmaxf(v.y, 0.f);
        s.z += fmaxf(v.z, 0.f); s.w += fmaxf(v.w, 0.f);
    }
    if (!FIN) {
        ((float4*)g_amsg)[idx] = s;
    } else {
        ushort4 hh, ll;
        split_bf16(s.x, hh.x, ll.x); split_bf16(s.y, hh.y, ll.y);
        split_bf16(s.z, hh.z, ll.z); split_bf16(s.w, hh.w, ll.w);
        size_t o = (size_t)a * K2P + j * 4;
        *(ushort4*)&gA2h[o] = hh;
        *(ushort4*)&gA2l[o] = ll;
    }
}

// ---------------- bond_msg: gA1 = split_bf16(a_msg[b2a] - relu(src[b2revb])) ----------------
template<int SRC>
__global__ void __launch_bounds__(256) bond_msg(
    const int* __restrict__ b2a, const int* __restrict__ b2revb)
{
    constexpr int G = K1P / 4;   // 80 groups of 4 cols
    const float* __restrict__ src = (SRC == 0) ? g_inp : g_msg;
    int idx = blockIdx.x * blockDim.x + threadIdx.x;
    if (idx >= N_BONDS * G) return;
    int m = idx / G;
    int g = idx - m * G;
    size_t o = (size_t)m * K1P + g * 4;
    if (g < HIDDEN / 4) {
        float4 av = ((const float4*)g_amsg)[(size_t)__ldg(&b2a[m]) * (HIDDEN/4) + g];
        float4 rv = ((const float4*)src   )[(size_t)__ldg(&b2revb[m]) * (HIDDEN/4) + g];
        float4 d = make_float4(av.x - fmaxf(rv.x, 0.f), av.y - fmaxf(rv.y, 0.f),
                               av.z - fmaxf(rv.z, 0.f), av.w - fmaxf(rv.w, 0.f));
        ushort4 hh, ll;
        split_bf16(d.x, hh.x, ll.x); split_bf16(d.y, hh.y, ll.y);
        split_bf16(d.z, hh.z, ll.z); split_bf16(d.w, hh.w, ll.w);
        *(ushort4*)&gA1h[o] = hh;
        *(ushort4*)&gA1l[o] = ll;
    } else {
        ushort4 z = make_ushort4(0, 0, 0, 0);
        *(ushort4*)&gA1h[o] = z;
        *(ushort4*)&gA1l[o] = z;
    }
}

// ---------------- per-molecule mean (mol_id sorted; deterministic) ----------------
__global__ void mol_mean(const int* __restrict__ mol_id, float* __restrict__ out)
{
    int mol = blockIdx.x;
    int lo = 0, hi = N_ATOMS;
    while (lo < hi) { int mid = (lo + hi) >> 1; if (mol_id[mid] < mol) lo = mid + 1; else hi = mid; }
    int start = lo;
    hi = N_ATOMS;
    while (lo < hi) { int mid = (lo + hi) >> 1; if (mol_id[mid] < mol + 1) lo = mid + 1; else hi = mid; }
    int end = lo;
    float inv = (end > start) ? 1.0f / (float)(end - start) : 0.0f;
    for (int j = threadIdx.x; j < HIDDEN; j += blockDim.x) {
        float s = 0.f;
        for (int a = start; a < end; a++) s += g_ah[(size_t)a * HIDDEN + j];
        out[(size_t)mol * HIDDEN + j] = s * inv;
    }
}

// ---------------- launch ----------------
extern "C" void kernel_launch(void* const* d_in, const int* in_sizes, int n_in,
                              void* d_out, int out_size)
{
    const float* f_atoms = (const float*)d_in[0];
    const float* f_bonds = (const float*)d_in[1];
    const int*   a2b     = (const int*)  d_in[2];
    const int*   b2a     = (const int*)  d_in[3];
    const int*   b2revb  = (const int*)  d_in[4];
    const int*   mol_id  = (const int*)  d_in[5];
    int wbase = (n_in >= 11 && in_sizes[6] == 1) ? 7 : 6;
    const float* W_i = (const float*)d_in[wbase + 0];
    const float* W_h = (const float*)d_in[wbase + 1];
    const float* W_o = (const float*)d_in[wbase + 2];
    const float* b_o = (const float*)d_in[wbase + 3];
    float* out = (float*)d_out;
    int n_mols = out_size / HIDDEN;

    cudaFuncSetAttribute(gemm_bf16<0>, cudaFuncAttributeMaxDynamicSharedMemorySize, SMEM_BYTES);
    cudaFuncSetAttribute(gemm_bf16<1>, cudaFuncAttributeMaxDynamicSharedMemorySize, SMEM_BYTES);
    cudaFuncSetAttribute(gemm_bf16<2>, cudaFuncAttributeMaxDynamicSharedMemorySize, SMEM_BYTES);

    dim3 gb(3, (N_BONDS + 127) / 128);
    dim3 ga(3, (N_ATOMS + 127) / 128);
    int atom_blocks = (N_ATOMS * (HIDDEN/4) + 255) / 256;
    int bond_blocks = (N_BONDS * (K1P/4) + 255) / 256;

    // GEMM 0: inp = f_bonds @ W_i   (message_0 = relu(inp) applied on read)
    conv_w<<<(K0P * NBP + 255) / 256, 256>>>(W_i, BOND_FDIM, K0P);
    conv_fbonds<<<((size_t)N_BONDS * K0P + 255) / 256, 256>>>(f_bonds);
    gemm_bf16<0><<<gb, 256, SMEM_BYTES>>>(nullptr, N_BONDS);

    // depth loop: msg_pre = inp + (a_msg[b2a]-relu(prev[b2revb])) @ W_h
    conv_w<<<(K1P * NBP + 255) / 256, 256>>>(W_h, HIDDEN, K1P);
    // d = 0: source = g_inp
    atom_sum<false, 0><<<atom_blocks, 256>>>(a2b);
    bond_msg<0><<<bond_blocks, 256>>>(b2a, b2revb);
    gemm_bf16<1><<<gb, 256, SMEM_BYTES>>>(nullptr, N_BONDS);
    // d = 1: source = g_msg
    atom_sum<false, 1><<<atom_blocks, 256>>>(a2b);
    bond_msg<1><<<bond_blocks, 256>>>(b2a, b2revb);
    gemm_bf16<1><<<gb, 256, SMEM_BYTES>>>(nullptr, N_BONDS);

    // readout: atom_hiddens = relu(concat @ W_o + b_o)
    atom_sum<true, 1><<<atom_blocks, 256>>>(a2b);
    conv_fatoms<<<((size_t)N_ATOMS * (K2P - HIDDEN) + 255) / 256, 256>>>(f_atoms);
    conv_w_o<<<(K2P * NBP + 255) / 256, 256>>>(W_o);
    gemm_bf16<2><<<ga, 256, SMEM_BYTES>>>(b_o, N_ATOMS);

    mol_mean<<<n_mols, 128>>>(mol_id, out);
}

// round 9
// speedup vs baseline: 1.2807x; 1.2346x over previous
#include <cuda_runtime.h>
#include <cuda_bf16.h>
#include <cstdint>

#define N_ATOMS   50000
#define N_BONDS   100000
#define MAX_NB    6
#define ATOM_FDIM 133
#define BOND_FDIM 147
#define HIDDEN    300
#define DEPTH     3

// padded K per GEMM (multiples of 32)
#define K0P 160   // bond_fdim 147 -> 160
#define K1P 320   // hidden 300 -> 320
#define K2P 448   // 300 + 133 = 433 -> 448  (A order: [amsg | f_atoms | pad])
#define NBP 384   // padded N for weight buffers

// ---------------- scratch (static device globals; no allocation) ----------------
__device__ float  g_inp [(size_t)N_BONDS * HIDDEN];   // W_i result (pre-activation)
__device__ float  g_msg [(size_t)N_BONDS * HIDDEN];   // pre-activation messages
__device__ float  g_amsg[(size_t)N_ATOMS * HIDDEN];
__device__ float  g_ah  [(size_t)N_ATOMS * HIDDEN];
__device__ __align__(16) ushort gA0h[(size_t)N_BONDS * K0P], gA0l[(size_t)N_BONDS * K0P];
__device__ __align__(16) ushort gA1h[(size_t)N_BONDS * K1P], gA1l[(size_t)N_BONDS * K1P];
__device__ __align__(16) ushort gA2h[(size_t)N_ATOMS * K2P], gA2l[(size_t)N_ATOMS * K2P];
__device__ __align__(16) ushort gWh [(size_t)K2P * NBP],     gWl [(size_t)K2P * NBP];

// ---------------- helpers ----------------
__device__ __forceinline__ uint32_t smem_u32(const void* p) {
    uint32_t a;
    asm("{ .reg .u64 t; cvta.to.shared.u64 t, %1; cvt.u32.u64 %0, t; }" : "=r"(a) : "l"(p));
    return a;
}
__device__ __forceinline__ void ldsm4(uint32_t* r, uint32_t addr) {
    asm volatile("ldmatrix.sync.aligned.m8n8.x4.shared.b16 {%0,%1,%2,%3}, [%4];"
        : "=r"(r[0]), "=r"(r[1]), "=r"(r[2]), "=r"(r[3]) : "r"(addr));
}
__device__ __forceinline__ void ldsm4t(uint32_t* r, uint32_t addr) {
    asm volatile("ldmatrix.sync.aligned.m8n8.x4.trans.shared.b16 {%0,%1,%2,%3}, [%4];"
        : "=r"(r[0]), "=r"(r[1]), "=r"(r[2]), "=r"(r[3]) : "r"(addr));
}
__device__ __forceinline__ void mma16816(float* c, const uint32_t* a, uint32_t b0, uint32_t b1) {
    asm volatile("mma.sync.aligned.m16n8k16.row.col.f32.bf16.bf16.f32 "
        "{%0,%1,%2,%3}, {%4,%5,%6,%7}, {%8,%9}, {%0,%1,%2,%3};"
        : "+f"(c[0]), "+f"(c[1]), "+f"(c[2]), "+f"(c[3])
        : "r"(a[0]), "r"(a[1]), "r"(a[2]), "r"(a[3]), "r"(b0), "r"(b1));
}
__device__ __forceinline__ void cp16(uint32_t dst, const void* src, bool pred) {
    asm volatile("cp.async.cg.shared.global [%0], [%1], 16, %2;"
        :: "r"(dst), "l"(src), "r"(pred ? 16 : 0) : "memory");
}
__device__ __forceinline__ void split_bf16(float v, ushort& h, ushort& l) {
    __nv_bfloat16 hb = __float2bfloat16(v);
    __nv_bfloat16 lb = __float2bfloat16(v - __bfloat162float(hb));
    h = __bfloat16_as_ushort(hb); l = __bfloat16_as_ushort(lb);
}

// ---------------- smem layout (BK = 32, 2 stages — R6 config) ----------------
constexpr int SA = 40, SB = 136;
constexpr int A_STG = 128 * SA * 2;              // 10240 B
constexpr int B_STG = 32 * SB * 2;               // 8704 B
constexpr int OFF_AH = 0;
constexpr int OFF_AL = 2 * A_STG;                // 20480
constexpr int OFF_BH = 4 * A_STG;                // 40960
constexpr int OFF_BL = OFF_BH + 2 * B_STG;       // 58368
constexpr int SMEM_BYTES = OFF_BL + 2 * B_STG;   // 75776

// ---------------- pipelined bf16 HMMA GEMM (R6 loop, HALF compile-time) ----------------
// C[M x 300] = epi(A @ B); BM=128, BN=128(/48), BK=32; 256 threads.
// HALF=false: n0 = blockIdx.x*128 (tiles 0,1). HALF=true: n0 = 256, cols 0..43 live.
// MODE 0: g_inp = acc;  MODE 1: g_msg = g_inp + acc;  MODE 2: g_ah = relu(acc+bias)
template<int MODE, bool HALF>
__global__ void __launch_bounds__(256) gemm_bf16(const float* __restrict__ bias, int M)
{
    constexpr int K = (MODE == 0) ? K0P : (MODE == 1) ? K1P : K2P;
    const ushort* __restrict__ Ahi = (MODE == 0) ? gA0h : (MODE == 1) ? gA1h : gA2h;
    const ushort* __restrict__ Alo = (MODE == 0) ? gA0l : (MODE == 1) ? gA1l : gA2l;

    extern __shared__ char sm[];
    const uint32_t sb = smem_u32(sm);
    const int tid = threadIdx.x, lane = tid & 31, wid = tid >> 5;
    const int m0 = blockIdx.y * 128;
    const int n0 = HALF ? 256 : blockIdx.x * 128;
    const int wm = wid & 3, wn = wid >> 2;

    float acc[2][8][4];
    #pragma unroll
    for (int i = 0; i < 2; i++)
        #pragma unroll
        for (int j = 0; j < 8; j++)
            #pragma unroll
            for (int q = 0; q < 4; q++) acc[i][j][q] = 0.f;

    constexpr int niter = K / 32;

    auto issue = [&](int it) {
        const int st = it & 1;
        const int k0 = it * 32;
        #pragma unroll
        for (int i = 0; i < 2; i++) {
            int q = i * 256 + tid;
            int row = q >> 2, c16 = q & 3;
            int gm = m0 + row;
            bool p = gm < M;
            size_t so = (size_t)(p ? gm : 0) * K + k0 + c16 * 8;
            uint32_t doff = (uint32_t)(row * SA + c16 * 8) * 2;
            cp16(sb + OFF_AH + st * A_STG + doff, Ahi + so, p);
            cp16(sb + OFF_AL + st * A_STG + doff, Alo + so, p);
        }
        #pragma unroll
        for (int i = 0; i < 2; i++) {
            int q = i * 256 + tid;
            int row = q >> 4, c16 = q & 15;
            bool bp = !HALF || (c16 < 6);    // compile-time for full tiles
            size_t so = (size_t)(k0 + row) * NBP + n0 + c16 * 8;
            uint32_t doff = (uint32_t)(row * SB + c16 * 8) * 2;
            cp16(sb + OFF_BH + st * B_STG + doff, gWh + so, bp);
            cp16(sb + OFF_BL + st * B_STG + doff, gWl + so, bp);
        }
        asm volatile("cp.async.commit_group;" ::: "memory");
    };

    issue(0);
    for (int it = 0; it < niter; it++) {
        if (it + 1 < niter) {
            issue(it + 1);
            asm volatile("cp.async.wait_group 1;" ::: "memory");
        } else {
            asm volatile("cp.async.wait_group 0;" ::: "memory");
        }
        __syncthreads();

        const int st = it & 1;
        const uint32_t aH = sb + OFF_AH + st * A_STG, aL = sb + OFF_AL + st * A_STG;
        const uint32_t bH = sb + OFF_BH + st * B_STG, bL = sb + OFF_BL + st * B_STG;
        if (!HALF || wn == 0) {
            #pragma unroll
            for (int ks = 0; ks < 2; ks++) {
                uint32_t ah[2][4], al[2][4], bh[4][4], bl[4][4];
                const int arow = wm * 32 + (lane & 15);
                const int acol = ks * 16 + (lane >> 4) * 8;
                #pragma unroll
                for (int mi = 0; mi < 2; mi++) {
                    uint32_t off = (uint32_t)((arow + mi * 16) * SA + acol) * 2;
                    ldsm4(ah[mi], aH + off);
                    ldsm4(al[mi], aL + off);
                }
                const int bkrow = ks * 16 + (lane & 15);
                const int bncol = wn * 64 + (lane >> 4) * 8;
                #pragma unroll
                for (int ni = 0; ni < 4; ni++) {
                    if (HALF && ni == 3) continue;   // compile-time
                    uint32_t off = (uint32_t)(bkrow * SB + bncol + ni * 16) * 2;
                    ldsm4t(bh[ni], bH + off);
                    ldsm4t(bl[ni], bL + off);
                }
                #pragma unroll
                for (int mi = 0; mi < 2; mi++) {
                    #pragma unroll
                    for (int p = 0; p < 4; p++) {
                        if (HALF && p == 3) continue;  // compile-time
                        mma16816(acc[mi][2*p],   ah[mi], bh[p][0], bh[p][1]);
                        mma16816(acc[mi][2*p],   ah[mi], bl[p][0], bl[p][1]);
                        mma16816(acc[mi][2*p],   al[mi], bh[p][0], bh[p][1]);
                        mma16816(acc[mi][2*p+1], ah[mi], bh[p][2], bh[p][3]);
                        mma16816(acc[mi][2*p+1], ah[mi], bl[p][2], bl[p][3]);
                        mma16816(acc[mi][2*p+1], al[mi], bh[p][2], bh[p][3]);
                    }
                }
            }
        }
        __syncthreads();
    }

    // ---- epilogue ----
    if (HALF && wn == 1) return;   // after last barrier; safe
    #pragma unroll
    for (int mi = 0; mi < 2; mi++) {
        #pragma unroll
        for (int t8 = 0; t8 < 8; t8++) {
            if (HALF && t8 >= 6) continue;   // cols >= 304 dead
            int col = n0 + wn * 64 + t8 * 8 + (lane & 3) * 2;
            #pragma unroll
            for (int h = 0; h < 2; h++) {
                int r = m0 + wm * 32 + mi * 16 + (lane >> 2) + h * 8;
                if (r >= M) continue;
                #pragma unroll
                for (int e = 0; e < 2; e++) {
                    int cn = col + e;
                    if (cn >= HIDDEN) continue;
                    float v = acc[mi][t8][2*h + e];
                    size_t o = (size_t)r * HIDDEN + cn;
                    if (MODE == 0)      { g_inp[o] = v; }
                    else if (MODE == 1) { g_msg[o] = g_inp[o] + v; }
                    else                { g_ah[o]  = fmaxf(v + bias[cn], 0.f); }
                }
            }
        }
    }
}

// ---------------- weight converters ----------------
__global__ void conv_w(const float* __restrict__ W, int K, int Kp)
{
    int idx = blockIdx.x * blockDim.x + threadIdx.x;
    if (idx >= Kp * NBP) return;
    int k = idx / NBP, n = idx - k * NBP;
    float v = (k < K && n < HIDDEN) ? W[(size_t)k * HIDDEN + n] : 0.f;
    ushort h, l; split_bf16(v, h, l);
    gWh[idx] = h; gWl[idx] = l;
}
__global__ void conv_w_o(const float* __restrict__ W)
{
    int idx = blockIdx.x * blockDim.x + threadIdx.x;
    if (idx >= K2P * NBP) return;
    int k = idx / NBP, n = idx - k * NBP;
    int src = (k < HIDDEN) ? (ATOM_FDIM + k) : (k < HIDDEN + ATOM_FDIM ? k - HIDDEN : -1);
    float v = (src >= 0 && n < HIDDEN) ? W[(size_t)src * HIDDEN + n] : 0.f;
    ushort h, l; split_bf16(v, h, l);
    gWh[idx] = h; gWl[idx] = l;
}

// ---------------- input converters ----------------
__global__ void conv_fbonds(const float* __restrict__ F)
{
    int idx = blockIdx.x * blockDim.x + threadIdx.x;
    if (idx >= N_BONDS * K0P) return;
    int r = idx / K0P, c = idx - r * K0P;
    float v = (c < BOND_FDIM) ? F[(size_t)r * BOND_FDIM + c] : 0.f;
    ushort h, l; split_bf16(v, h, l);
    gA0h[idx] = h; gA0l[idx] = l;
}
__global__ void conv_fatoms(const float* __restrict__ F)
{
    constexpr int C = K2P - HIDDEN;  // 148
    int idx = blockIdx.x * blockDim.x + threadIdx.x;
    if (idx >= N_ATOMS * C) return;
    int a = idx / C, c = idx - a * C;
    float v = (c < ATOM_FDIM) ? F[(size_t)a * ATOM_FDIM + c] : 0.f;
    ushort h, l; split_bf16(v, h, l);
    size_t o = (size_t)a * K2P + HIDDEN + c;
    gA2h[o] = h; gA2l[o] = l;
}

// ---------------- atom_sum: a_msg[a] = sum_k relu(src[a2b[a][k]]) ----------------
template<bool FIN, int SRC>
__global__ void __launch_bounds__(256) atom_sum(const int* __restrict__ a2b)
{
    constexpr int HV = HIDDEN / 4;
    const float* __restrict__ src = (SRC == 0) ? g_inp : g_msg;
    int idx = blockIdx.x * blockDim.x + threadIdx.x;
    if (idx >= N_ATOMS * HV) return;
    int a = idx / HV;
    int j = idx - a * HV;
    const float4* m4 = (const float4*)src;
    float4 s = make_float4(0.f, 0.f, 0.f, 0.f);
    #pragma unroll
    for (int k = 0; k < MAX_NB; k++) {
        int b = __ldg(&a2b[a * MAX_NB + k]);
        float4 v = m4[(size_t)b * HV + j];
        s.x += fmaxf(v.x, 0.f); s.y += fmaxf(v.y, 0.f);
        s.z += fmaxf(v.z, 0.f); s.w += fmaxf(v.w, 0.f);
    }
    if (!FIN) {
        ((float4*)g_amsg)[idx] = s;
    } else {
        ushort4 hh, ll;
        split_bf16(s.x, hh.x, ll.x); split_bf16(s.y, hh.y, ll.y);
        split_bf16(s.z, hh.z, ll.z); split_bf16(s.w, hh.w, ll.w);
        size_t o = (size_t)a * K2P + j * 4;
        *(ushort4*)&gA2h[o] = hh;
        *(ushort4*)&gA2l[o] = ll;
    }
}

// ---------------- bond_msg: gA1 = split_bf16(a_msg[b2a] - relu(src[b2revb])) ----------------
template<int SRC>
__global__ void __launch_bounds__(256) bond_msg(
    const int* __restrict__ b2a, const int* __restrict__ b2revb)
{
    constexpr int G = K1P / 4;
    const float* __restrict__ src = (SRC == 0) ? g_inp : g_msg;
    int idx = blockIdx.x * blockDim.x + threadIdx.x;
    if (idx >= N_BONDS * G) return;
    int m = idx / G;
    int g = idx - m * G;
    size_t o = (size_t)m * K1P + g * 4;
    if (g < HIDDEN / 4) {
        float4 av = ((const float4*)g_amsg)[(size_t)__ldg(&b2a[m]) * (HIDDEN/4) + g];
        float4 rv = ((const float4*)src   )[(size_t)__ldg(&b2revb[m]) * (HIDDEN/4) + g];
        float4 d = make_float4(av.x - fmaxf(rv.x, 0.f), av.y - fmaxf(rv.y, 0.f),
                               av.z - fmaxf(rv.z, 0.f), av.w - fmaxf(rv.w, 0.f));
        ushort4 hh, ll;
        split_bf16(d.x, hh.x, ll.x); split_bf16(d.y, hh.y, ll.y);
        split_bf16(d.z, hh.z, ll.z); split_bf16(d.w, hh.w, ll.w);
        *(ushort4*)&gA1h[o] = hh;
        *(ushort4*)&gA1l[o] = ll;
    } else {
        ushort4 z = make_ushort4(0, 0, 0, 0);
        *(ushort4*)&gA1h[o] = z;
        *(ushort4*)&gA1l[o] = z;
    }
}

// ---------------- per-molecule mean (mol_id sorted; deterministic) ----------------
__global__ void mol_mean(const int* __restrict__ mol_id, float* __restrict__ out)
{
    int mol = blockIdx.x;
    int lo = 0, hi = N_ATOMS;
    while (lo < hi) { int mid = (lo + hi) >> 1; if (mol_id[mid] < mol) lo = mid + 1; else hi = mid; }
    int start = lo;
    hi = N_ATOMS;
    while (lo < hi) { int mid = (lo + hi) >> 1; if (mol_id[mid] < mol + 1) lo = mid + 1; else hi = mid; }
    int end = lo;
    float inv = (end > start) ? 1.0f / (float)(end - start) : 0.0f;
    for (int j = threadIdx.x; j < HIDDEN; j += blockDim.x) {
        float s = 0.f;
        for (int a = start; a < end; a++) s += g_ah[(size_t)a * HIDDEN + j];
        out[(size_t)mol * HIDDEN + j] = s * inv;
    }
}

// ---------------- launch ----------------
extern "C" void kernel_launch(void* const* d_in, const int* in_sizes, int n_in,
                              void* d_out, int out_size)
{
    const float* f_atoms = (const float*)d_in[0];
    const float* f_bonds = (const float*)d_in[1];
    const int*   a2b     = (const int*)  d_in[2];
    const int*   b2a     = (const int*)  d_in[3];
    const int*   b2revb  = (const int*)  d_in[4];
    const int*   mol_id  = (const int*)  d_in[5];
    int wbase = (n_in >= 11 && in_sizes[6] == 1) ? 7 : 6;
    const float* W_i = (const float*)d_in[wbase + 0];
    const float* W_h = (const float*)d_in[wbase + 1];
    const float* W_o = (const float*)d_in[wbase + 2];
    const float* b_o = (const float*)d_in[wbase + 3];
    float* out = (float*)d_out;
    int n_mols = out_size / HIDDEN;

    cudaFuncSetAttribute(gemm_bf16<0,false>, cudaFuncAttributeMaxDynamicSharedMemorySize, SMEM_BYTES);
    cudaFuncSetAttribute(gemm_bf16<0,true >, cudaFuncAttributeMaxDynamicSharedMemorySize, SMEM_BYTES);
    cudaFuncSetAttribute(gemm_bf16<1,false>, cudaFuncAttributeMaxDynamicSharedMemorySize, SMEM_BYTES);
    cudaFuncSetAttribute(gemm_bf16<1,true >, cudaFuncAttributeMaxDynamicSharedMemorySize, SMEM_BYTES);
    cudaFuncSetAttribute(gemm_bf16<2,false>, cudaFuncAttributeMaxDynamicSharedMemorySize, SMEM_BYTES);
    cudaFuncSetAttribute(gemm_bf16<2,true >, cudaFuncAttributeMaxDynamicSharedMemorySize, SMEM_BYTES);

    int mb = (N_BONDS + 127) / 128;   // 782
    int ma = (N_ATOMS + 127) / 128;   // 391
    dim3 gbF(2, mb), gbH(1, mb), gaF(2, ma), gaH(1, ma);
    int atom_blocks = (N_ATOMS * (HIDDEN/4) + 255) / 256;
    int bond_blocks = (N_BONDS * (K1P/4) + 255) / 256;

    // GEMM 0: inp = f_bonds @ W_i
    conv_w<<<(K0P * NBP + 255) / 256, 256>>>(W_i, BOND_FDIM, K0P);
    conv_fbonds<<<((size_t)N_BONDS * K0P + 255) / 256, 256>>>(f_bonds);
    gemm_bf16<0,false><<<gbF, 256, SMEM_BYTES>>>(nullptr, N_BONDS);
    gemm_bf16<0,true ><<<gbH, 256, SMEM_BYTES>>>(nullptr, N_BONDS);

    // depth loop: msg_pre = inp + (a_msg[b2a]-relu(prev[b2revb])) @ W_h
    conv_w<<<(K1P * NBP + 255) / 256, 256>>>(W_h, HIDDEN, K1P);
    atom_sum<false, 0><<<atom_blocks, 256>>>(a2b);
    bond_msg<0><<<bond_blocks, 256>>>(b2a, b2revb);
    gemm_bf16<1,false><<<gbF, 256, SMEM_BYTES>>>(nullptr, N_BONDS);
    gemm_bf16<1,true ><<<gbH, 256, SMEM_BYTES>>>(nullptr, N_BONDS);
    atom_sum<false, 1><<<atom_blocks, 256>>>(a2b);
    bond_msg<1><<<bond_blocks, 256>>>(b2a, b2revb);
    gemm_bf16<1,false><<<gbF, 256, SMEM_BYTES>>>(nullptr, N_BONDS);
    gemm_bf16<1,true ><<<gbH, 256, SMEM_BYTES>>>(nullptr, N_BONDS);

    // readout
    atom_sum<true, 1><<<atom_blocks, 256>>>(a2b);
    conv_fatoms<<<((size_t)N_ATOMS * (K2P - HIDDEN) + 255) / 256, 256>>>(f_atoms);
    conv_w_o<<<(K2P * NBP + 255) / 256, 256>>>(W_o);
    gemm_bf16<2,false><<<gaF, 256, SMEM_BYTES>>>(b_o, N_ATOMS);
    gemm_bf16<2,true ><<<gaH, 256, SMEM_BYTES>>>(b_o, N_ATOMS);

    mol_mean<<<n_mols, 128>>>(mol_id, out);
}